// round 1
// baseline (speedup 1.0000x reference)
#include <cuda_runtime.h>

#define NB 4
#define NL 1024
#define ND 256
#define NH 8
#define NHD 2048          // H*D
#define NBL 4096          // B*L

// ---------------- scratch (device globals: no allocs allowed) ----------------
static __device__ float g_qh[(size_t)NBL * NHD];
static __device__ float g_kh[(size_t)NBL * NHD];
static __device__ float g_vh[(size_t)NBL * NHD];
static __device__ float g_ho[(size_t)NBL * NHD];
static __device__ float g_tmp[(size_t)4 * NBL * ND];   // split-K partials for fc

// =============================================================================
// Generic 128x128 SGEMM, C = A @ B^T (TRANSB=1) or A @ B (TRANSB=0).
// 256 threads, 8x8 microtile per thread, BK=16, double-buffered smem.
// Batched over blockIdx.z with two-stride (b,h) offset decomposition.
// EPI=0: plain store.  EPI=1: scores epilogue (scale 1/16, clip +-15, mask;
//        masked entries stored as sentinel 3e4 for the softmax pass).
// All problem dims here are multiples of 128 (M,N) and 16 (K): no guards.
// =============================================================================
template <bool TRANSB, int EPI>
__global__ void __launch_bounds__(256, 2) gemm128(
    const float* __restrict__ Ag, int lda,
    const float* __restrict__ Bg, int ldb,
    float* __restrict__ Cg, int ldc,
    int K, int nBdim,
    long sAb, long sAh, long sBb, long sBh, long sCb, long sCh,
    const int* __restrict__ maskg, long sMb)
{
    __shared__ __align__(16) float As[2][16][128];
    __shared__ __align__(16) float Bs[2][16][128];

    const int z  = blockIdx.z;
    const int zb = z % nBdim;
    const int zh = z / nBdim;
    const float* A  = Ag + (size_t)zb * sAb + (size_t)zh * sAh;
    const float* Bp = Bg + (size_t)zb * sBb + (size_t)zh * sBh;
    float*       C  = Cg + (size_t)zb * sCb + (size_t)zh * sCh;

    const int rowBase = blockIdx.y * 128;
    const int colBase = blockIdx.x * 128;
    const int tid = threadIdx.x;
    const int tx = tid & 15;
    const int ty = tid >> 4;

    // global->smem load mapping
    const int ar = tid >> 1;          // row within A tile (0..127)
    const int ac = (tid & 1) * 8;     // k-col within A tile (0 or 8)
    const int br_n = tid >> 4;        // k-row within B tile (!TRANSB) 0..15
    const int bc_n = (tid & 15) * 8;  // n-col within B tile (!TRANSB)

    float acc[8][8];
#pragma unroll
    for (int i = 0; i < 8; i++)
#pragma unroll
        for (int j = 0; j < 8; j++) acc[i][j] = 0.f;

    const int T = K >> 4;
    float4 a0, a1, b0, b1;

    auto gload = [&](int t) {
        const int ko = t * 16;
        const float* ap = A + (size_t)(rowBase + ar) * lda + ko + ac;
        a0 = *(const float4*)ap;
        a1 = *(const float4*)(ap + 4);
        if (TRANSB) {
            const float* bp = Bp + (size_t)(colBase + ar) * ldb + ko + ac;
            b0 = *(const float4*)bp;
            b1 = *(const float4*)(bp + 4);
        } else {
            const float* bp = Bp + (size_t)(ko + br_n) * ldb + colBase + bc_n;
            b0 = *(const float4*)bp;
            b1 = *(const float4*)(bp + 4);
        }
    };
    auto sstore = [&](int buf) {
        float av[8] = {a0.x, a0.y, a0.z, a0.w, a1.x, a1.y, a1.z, a1.w};
#pragma unroll
        for (int i = 0; i < 8; i++) As[buf][ac + i][ar] = av[i];
        if (TRANSB) {
            float bv[8] = {b0.x, b0.y, b0.z, b0.w, b1.x, b1.y, b1.z, b1.w};
#pragma unroll
            for (int i = 0; i < 8; i++) Bs[buf][ac + i][ar] = bv[i];
        } else {
            *(float4*)&Bs[buf][br_n][bc_n]     = b0;
            *(float4*)&Bs[buf][br_n][bc_n + 4] = b1;
        }
    };

    gload(0);
    sstore(0);
    __syncthreads();

    for (int t = 0; t < T; t++) {
        const int cur = t & 1;
        if (t + 1 < T) gload(t + 1);
#pragma unroll
        for (int kk = 0; kk < 16; kk++) {
            float a[8], b[8];
            *(float4*)&a[0] = *(const float4*)&As[cur][kk][ty * 8];
            *(float4*)&a[4] = *(const float4*)&As[cur][kk][ty * 8 + 4];
            *(float4*)&b[0] = *(const float4*)&Bs[cur][kk][tx * 8];
            *(float4*)&b[4] = *(const float4*)&Bs[cur][kk][tx * 8 + 4];
#pragma unroll
            for (int i = 0; i < 8; i++)
#pragma unroll
                for (int j = 0; j < 8; j++)
                    acc[i][j] = fmaf(a[i], b[j], acc[i][j]);
        }
        if (t + 1 < T) sstore(cur ^ 1);
        __syncthreads();
    }

    if (EPI == 0) {
#pragma unroll
        for (int i = 0; i < 8; i++) {
            float* cp = C + (size_t)(rowBase + ty * 8 + i) * ldc + colBase + tx * 8;
            float4 v0 = {acc[i][0], acc[i][1], acc[i][2], acc[i][3]};
            float4 v1 = {acc[i][4], acc[i][5], acc[i][6], acc[i][7]};
            *(float4*)cp       = v0;
            *(float4*)(cp + 4) = v1;
        }
    } else {
        // scores epilogue: x = clip(S/16, -15, 15); masked -> sentinel 3e4
        const int* mb = maskg + (size_t)zb * sMb;
#pragma unroll
        for (int i = 0; i < 8; i++) {
            const int r = rowBase + ty * 8 + i;
            const int4* mp = (const int4*)(mb + (size_t)r * NL + colBase + tx * 8);
            int4 m0 = mp[0];
            int4 m1 = mp[1];
            int mm[8] = {m0.x, m0.y, m0.z, m0.w, m1.x, m1.y, m1.z, m1.w};
            float v[8];
#pragma unroll
            for (int j = 0; j < 8; j++) {
                float s = acc[i][j] * 0.0625f;            // 1/sqrt(256)
                s = fminf(15.f, fmaxf(-15.f, s));
                v[j] = mm[j] ? s : 30000.f;
            }
            float* cp = C + (size_t)r * ldc + colBase + tx * 8;
            *(float4*)cp       = *(float4*)&v[0];
            *(float4*)(cp + 4) = *(float4*)&v[4];
        }
    }
}

// =============================================================================
// In-place row softmax over attn region. One block (256 thr) per row of 1024.
// Sentinel (>1e3) = masked: contributes 0 to the row max (matching reference's
// clip*mask before max) and 0 to the exp/sum.
// =============================================================================
__global__ void __launch_bounds__(256) softmax_k(float* __restrict__ attn)
{
    __shared__ float sh[8];
    float* p = attn + (size_t)blockIdx.x * 1024;
    const int t = threadIdx.x;

    float4 v4 = ((const float4*)p)[t];
    float x[4] = {v4.x, v4.y, v4.z, v4.w};
    bool  msk[4];
    float mx = -1e30f;
#pragma unroll
    for (int i = 0; i < 4; i++) {
        msk[i] = (x[i] > 1000.f);
        if (msk[i]) x[i] = 0.f;       // masked entries are exactly 0 in ref's max
        mx = fmaxf(mx, x[i]);
    }
#pragma unroll
    for (int o = 16; o; o >>= 1) mx = fmaxf(mx, __shfl_xor_sync(0xffffffffu, mx, o));
    if ((t & 31) == 0) sh[t >> 5] = mx;
    __syncthreads();
    mx = sh[0];
#pragma unroll
    for (int i = 1; i < 8; i++) mx = fmaxf(mx, sh[i]);

    float e[4];
    float s = 0.f;
#pragma unroll
    for (int i = 0; i < 4; i++) {
        e[i] = msk[i] ? 0.f : __expf(x[i] - mx);
        s += e[i];
    }
#pragma unroll
    for (int o = 16; o; o >>= 1) s += __shfl_xor_sync(0xffffffffu, s, o);
    __syncthreads();
    if ((t & 31) == 0) sh[t >> 5] = s;
    __syncthreads();
    s = 0.f;
#pragma unroll
    for (int i = 0; i < 8; i++) s += sh[i];

    const float inv = 1.f / (s + 1e-6f);
    float4 o4 = {e[0] * inv, e[1] * inv, e[2] * inv, e[3] * inv};
    ((float4*)p)[t] = o4;
}

// =============================================================================
// Reduce 4 split-K fc partials + fc bias + residual, then LayerNorm.
// One block (256 thr) per output row of D=256.
// =============================================================================
__global__ void __launch_bounds__(256) fc_ln_k(
    const float* __restrict__ tmp, const float* __restrict__ fcb,
    const float* __restrict__ resid, const float* __restrict__ lg,
    const float* __restrict__ lb, float* __restrict__ out)
{
    __shared__ float shs[8], shq[8];
    const size_t o = (size_t)blockIdx.x * 256 + threadIdx.x;
    const int t = threadIdx.x;

    float v = tmp[o] + tmp[o + 1048576] + tmp[o + 2097152] + tmp[o + 3145728]
            + fcb[t] + resid[o];

    float s = v, qq = v * v;
#pragma unroll
    for (int d = 16; d; d >>= 1) {
        s  += __shfl_xor_sync(0xffffffffu, s, d);
        qq += __shfl_xor_sync(0xffffffffu, qq, d);
    }
    if ((t & 31) == 0) { shs[t >> 5] = s; shq[t >> 5] = qq; }
    __syncthreads();
    s = 0.f; qq = 0.f;
#pragma unroll
    for (int i = 0; i < 8; i++) { s += shs[i]; qq += shq[i]; }

    const float mean = s * (1.f / 256.f);
    const float var  = qq * (1.f / 256.f) - mean * mean;
    out[o] = (v - mean) * rsqrtf(var + 1e-5f) * lg[t] + lb[t];
}

// =============================================================================
extern "C" void kernel_launch(void* const* d_in, const int* in_sizes, int n_in,
                              void* d_out, int out_size)
{
    const float* q    = (const float*)d_in[0];
    const int*   mask = (const int*)  d_in[1];
    const float* k    = (const float*)d_in[2];
    const float* v    = (const float*)d_in[3];
    const float* w_qs = (const float*)d_in[4];
    const float* w_ks = (const float*)d_in[5];
    const float* w_vs = (const float*)d_in[6];
    const float* fc_w = (const float*)d_in[7];
    const float* fc_b = (const float*)d_in[8];
    const float* ln_g = (const float*)d_in[9];
    const float* ln_b = (const float*)d_in[10];

    float* out  = (float*)d_out;
    float* attn = out + (size_t)NBL * ND;   // output tuple: [out | attn_hb]

    float *qh, *kh, *vh, *ho, *tmp;
    cudaGetSymbolAddress((void**)&qh,  g_qh);
    cudaGetSymbolAddress((void**)&kh,  g_kh);
    cudaGetSymbolAddress((void**)&vh,  g_vh);
    cudaGetSymbolAddress((void**)&ho,  g_ho);
    cudaGetSymbolAddress((void**)&tmp, g_tmp);

    dim3 thr(256);

    // 1) projections: [4096,256] @ [2048,256]^T -> [4096,2048]
    gemm128<true, 0><<<dim3(NHD / 128, NBL / 128, 1), thr>>>(
        q, ND, w_qs, ND, qh, NHD, ND, 1, 0, 0, 0, 0, 0, 0, nullptr, 0);
    gemm128<true, 0><<<dim3(NHD / 128, NBL / 128, 1), thr>>>(
        k, ND, w_ks, ND, kh, NHD, ND, 1, 0, 0, 0, 0, 0, 0, nullptr, 0);
    gemm128<true, 0><<<dim3(NHD / 128, NBL / 128, 1), thr>>>(
        v, ND, w_vs, ND, vh, NHD, ND, 1, 0, 0, 0, 0, 0, 0, nullptr, 0);

    // 2) scores per (b,h): Qh @ Kh^T / 16, clip, mask -> attn region (z = h*B+b)
    gemm128<true, 1><<<dim3(NL / 128, NL / 128, NB * NH), thr>>>(
        qh, NHD, kh, NHD, attn, NL, ND, NB,
        (long)NL * NHD, (long)ND,            // A: b*L*HD + h*D
        (long)NL * NHD, (long)ND,            // B: same
        (long)NL * NL, (long)NB * NL * NL,   // C: z*L*L
        mask, (long)NL * NL);

    // 3) masked softmax, in place
    softmax_k<<<NH * NB * NL, 256>>>(attn);

    // 4) attn @ Vh -> head outputs [B,L,H,D]
    gemm128<false, 0><<<dim3(ND / 128, NL / 128, NB * NH), thr>>>(
        attn, NL, vh, NHD, ho, NHD, NL, NB,
        (long)NL * NL, (long)NB * NL * NL,
        (long)NL * NHD, (long)ND,
        (long)NL * NHD, (long)ND,
        nullptr, 0);

    // 5) fc: [4096,2048] @ [256,2048]^T, split-K=4 -> partials in g_tmp
    gemm128<true, 0><<<dim3(ND / 128, NBL / 128, 4), thr>>>(
        ho, NHD, fc_w, NHD, tmp, ND, NHD / 4, 1,
        0, 512,                // A k-offset per split
        0, 512,                // B k-offset per split
        0, (long)NBL * ND,     // C partial-buffer offset per split
        nullptr, 0);

    // 6) reduce partials + bias + residual + LayerNorm -> out
    fc_ln_k<<<NBL, 256>>>(tmp, fc_b, q, ln_g, ln_b, out);
}

// round 3
// speedup vs baseline: 1.3359x; 1.3359x over previous
#include <cuda_runtime.h>
#include <cuda_bf16.h>
#include <mma.h>
#include <cstdint>

using namespace nvcuda;

#define NB 4
#define NL 1024
#define ND 256
#define NH 8
#define NHD 2048
#define NBL 4096

#define LDS_AB 40            // smem leading dim (32 + 8 pad) -> 80B rows, conflict-free
#define APL (128 * LDS_AB)   // elems per (buffer,plane) tile
#define LDC_S 132            // epilogue smem stride (floats)
#define SMEMB 81920          // 2 buf * 2 planes * (A+B) tiles = 81920B >= Cs 67584B

// ---------------------------------------------------------------------------
// scratch (device globals — allocations forbidden)
// ---------------------------------------------------------------------------
static __device__ __align__(16) __nv_bfloat16 g_qp[2 * NBL * ND];
static __device__ __align__(16) __nv_bfloat16 g_kp[2 * NBL * ND];
static __device__ __align__(16) __nv_bfloat16 g_vp[2 * NBL * ND];
static __device__ __align__(16) __nv_bfloat16 g_wqp[2 * NHD * ND];
static __device__ __align__(16) __nv_bfloat16 g_wkp[2 * NHD * ND];
static __device__ __align__(16) __nv_bfloat16 g_wvp[2 * NHD * ND];
static __device__ __align__(16) __nv_bfloat16 g_fcwp[2 * ND * NHD];
static __device__ __align__(16) __nv_bfloat16 g_qhp[2 * (size_t)NBL * NHD];
static __device__ __align__(16) __nv_bfloat16 g_khp[2 * (size_t)NBL * NHD];
static __device__ __align__(16) __nv_bfloat16 g_vht[2 * (size_t)NHD * NBL];
static __device__ __align__(16) __nv_bfloat16 g_hop[2 * (size_t)NBL * NHD];
static __device__ float g_tmp[(size_t)4 * NBL * ND];

// ---------------------------------------------------------------------------
// fp32 -> (hi, lo) bf16 planes
// ---------------------------------------------------------------------------
__global__ void __launch_bounds__(256) cvt_k(const float* __restrict__ x,
                                             __nv_bfloat16* __restrict__ hi,
                                             __nv_bfloat16* __restrict__ lo, int n4) {
    int i = blockIdx.x * 256 + threadIdx.x;
    if (i >= n4) return;
    float4 v = *((const float4*)x + i);
    float f[4] = {v.x, v.y, v.z, v.w};
    __align__(8) __nv_bfloat16 h[4], l[4];
#pragma unroll
    for (int j = 0; j < 4; j++) {
        h[j] = __float2bfloat16(f[j]);
        l[j] = __float2bfloat16(f[j] - __bfloat162float(h[j]));
    }
    *(uint2*)(hi + (size_t)i * 4) = *(uint2*)h;
    *(uint2*)(lo + (size_t)i * 4) = *(uint2*)l;
}

// ---------------------------------------------------------------------------
// WMMA bf16x3 GEMM: C[128x128 tile] = A @ B^T, fp32 accumulate.
//   A: bf16 hi/lo planes (ACVT=0) or fp32 split on the fly (ACVT=1)
//   B: bf16 hi/lo planes, [N,K] K-major
//   EPI 0: write bf16 hi/lo pairs   1: scores (scale/clip/mask -> sentinel)
//   EPI 3: plain fp32 (fc split-K partials)
// 256 threads (8 warps, 2x4), warp tile 64x32, BK=32, double-buffered SMEM.
// ---------------------------------------------------------------------------
template <int ACVT, int EPI>
__global__ void __launch_bounds__(256, 1) tgemm(
    const void* __restrict__ Agv, long Asplit, int lda,
    const __nv_bfloat16* __restrict__ Bg, long Bsplit, int ldb,
    void* __restrict__ Cgv, int ldc, long Csplit,
    int K, int nBdim,
    long sAb, long sAh, long sBb, long sBh, long sCb, long sCh,
    const int* __restrict__ maskg, long sMb)
{
    extern __shared__ __align__(16) char sm[];
    __nv_bfloat16* Abuf = (__nv_bfloat16*)sm;          // [buf][plane][128*40]
    __nv_bfloat16* Bbuf = Abuf + 4 * APL;
    float* Cs = (float*)sm;                            // epilogue staging (reuse)

    const int tid = threadIdx.x;
    const int wid = tid >> 5;
    const int wm = wid & 1;       // warp row (2 x 64)
    const int wn = wid >> 1;      // warp col (4 x 32)

    const int z = blockIdx.z, zb = z % nBdim, zh = z / nBdim;
    const float* Af = ACVT ? (const float*)Agv + (size_t)zb * sAb + (size_t)zh * sAh : nullptr;
    const __nv_bfloat16* Ah =
        ACVT ? nullptr : (const __nv_bfloat16*)Agv + (size_t)zb * sAb + (size_t)zh * sAh;
    const __nv_bfloat16* Bp = Bg + (size_t)zb * sBb + (size_t)zh * sBh;

    const int rowBase = blockIdx.y * 128;
    const int colBase = blockIdx.x * 128;

    wmma::fragment<wmma::accumulator, 16, 16, 16, float> acc[4][2];
#pragma unroll
    for (int i = 0; i < 4; i++)
#pragma unroll
        for (int j = 0; j < 2; j++) wmma::fill_fragment(acc[i][j], 0.f);

    // ---- staging registers for global loads (tile 128x32 = 512 uint4/plane) ----
    uint4  rA[2][2], rB[2][2];      // [c-iter][plane]
    float4 rAf[2][2];               // ACVT: [c-iter][half]

    auto ldgA = [&](int t) {
        const int ko = t * 32;
#pragma unroll
        for (int i = 0; i < 2; i++) {
            const int c = tid + i * 256, row = c >> 2, col8 = (c & 3) * 8;
            if (ACVT) {
                const float* p = Af + (size_t)(rowBase + row) * lda + ko + col8;
                rAf[i][0] = *(const float4*)p;
                rAf[i][1] = *(const float4*)(p + 4);
            } else {
                const __nv_bfloat16* p = Ah + (size_t)(rowBase + row) * lda + ko + col8;
                rA[i][0] = *(const uint4*)p;
                rA[i][1] = *(const uint4*)(p + Asplit);
            }
        }
    };
    auto ldgB = [&](int t) {
        const int ko = t * 32;
#pragma unroll
        for (int i = 0; i < 2; i++) {
            const int c = tid + i * 256, row = c >> 2, col8 = (c & 3) * 8;
            const __nv_bfloat16* p = Bp + (size_t)(colBase + row) * ldb + ko + col8;
            rB[i][0] = *(const uint4*)p;
            rB[i][1] = *(const uint4*)(p + Bsplit);
        }
    };
    auto stsAB = [&](int buf) {
#pragma unroll
        for (int i = 0; i < 2; i++) {
            const int c = tid + i * 256, row = c >> 2, col8 = (c & 3) * 8;
            const int off = row * LDS_AB + col8;
            if (ACVT) {
                float fv[8] = {rAf[i][0].x, rAf[i][0].y, rAf[i][0].z, rAf[i][0].w,
                               rAf[i][1].x, rAf[i][1].y, rAf[i][1].z, rAf[i][1].w};
                __align__(16) __nv_bfloat16 hv[8], lv[8];
#pragma unroll
                for (int j = 0; j < 8; j++) {
                    hv[j] = __float2bfloat16(fv[j]);
                    lv[j] = __float2bfloat16(fv[j] - __bfloat162float(hv[j]));
                }
                *(uint4*)(Abuf + (buf * 2 + 0) * APL + off) = *(uint4*)hv;
                *(uint4*)(Abuf + (buf * 2 + 1) * APL + off) = *(uint4*)lv;
            } else {
                *(uint4*)(Abuf + (buf * 2 + 0) * APL + off) = rA[i][0];
                *(uint4*)(Abuf + (buf * 2 + 1) * APL + off) = rA[i][1];
            }
            *(uint4*)(Bbuf + (buf * 2 + 0) * APL + off) = rB[i][0];
            *(uint4*)(Bbuf + (buf * 2 + 1) * APL + off) = rB[i][1];
        }
    };
    auto compute = [&](int buf) {
        const __nv_bfloat16* Ah0 = Abuf + (buf * 2 + 0) * APL + wm * 64 * LDS_AB;
        const __nv_bfloat16* Al0 = Abuf + (buf * 2 + 1) * APL + wm * 64 * LDS_AB;
        const __nv_bfloat16* Bh0 = Bbuf + (buf * 2 + 0) * APL + wn * 32 * LDS_AB;
        const __nv_bfloat16* Bl0 = Bbuf + (buf * 2 + 1) * APL + wn * 32 * LDS_AB;
#pragma unroll
        for (int ks = 0; ks < 2; ks++) {
            wmma::fragment<wmma::matrix_a, 16, 16, 16, __nv_bfloat16, wmma::row_major> fah[4], fal[4];
            wmma::fragment<wmma::matrix_b, 16, 16, 16, __nv_bfloat16, wmma::col_major> fbh[2], fbl[2];
#pragma unroll
            for (int i = 0; i < 4; i++) {
                wmma::load_matrix_sync(fah[i], Ah0 + i * 16 * LDS_AB + ks * 16, LDS_AB);
                wmma::load_matrix_sync(fal[i], Al0 + i * 16 * LDS_AB + ks * 16, LDS_AB);
            }
#pragma unroll
            for (int j = 0; j < 2; j++) {
                wmma::load_matrix_sync(fbh[j], Bh0 + j * 16 * LDS_AB + ks * 16, LDS_AB);
                wmma::load_matrix_sync(fbl[j], Bl0 + j * 16 * LDS_AB + ks * 16, LDS_AB);
            }
#pragma unroll
            for (int i = 0; i < 4; i++)
#pragma unroll
                for (int j = 0; j < 2; j++) {
                    wmma::mma_sync(acc[i][j], fah[i], fbh[j], acc[i][j]);
                    wmma::mma_sync(acc[i][j], fah[i], fbl[j], acc[i][j]);
                    wmma::mma_sync(acc[i][j], fal[i], fbh[j], acc[i][j]);
                }
        }
    };

    // ---- mainloop: double-buffered ----
    const int T = K >> 5;
    ldgA(0); ldgB(0);
    stsAB(0);
    __syncthreads();

    for (int t = 0; t < T; t++) {
        if (t + 1 < T) { ldgA(t + 1); ldgB(t + 1); }
        compute(t & 1);
        if (t + 1 < T) {
            __syncthreads();
            stsAB((t + 1) & 1);
            __syncthreads();
        }
    }

    // ---- epilogue: stage accumulators through SMEM ----
    __syncthreads();
#pragma unroll
    for (int i = 0; i < 4; i++)
#pragma unroll
        for (int j = 0; j < 2; j++)
            wmma::store_matrix_sync(Cs + (size_t)(wm * 64 + i * 16) * LDC_S + wn * 32 + j * 16,
                                    acc[i][j], LDC_S, wmma::mem_row_major);
    __syncthreads();

    const int row = tid >> 1;
    const int ch  = (tid & 1) * 64;
    const float* crow = Cs + (size_t)row * LDC_S + ch;
    const int gr = rowBase + row;
    const int gc = colBase + ch;

    if (EPI == 0) {
        __nv_bfloat16* Ch = (__nv_bfloat16*)Cgv + (size_t)zb * sCb + (size_t)zh * sCh +
                            (size_t)gr * ldc + gc;
#pragma unroll
        for (int cb = 0; cb < 64; cb += 8) {
            __align__(16) __nv_bfloat16 hv[8], lv[8];
#pragma unroll
            for (int j = 0; j < 8; j++) {
                float v = crow[cb + j];
                hv[j] = __float2bfloat16(v);
                lv[j] = __float2bfloat16(v - __bfloat162float(hv[j]));
            }
            *(uint4*)(Ch + cb)          = *(uint4*)hv;
            *(uint4*)(Ch + Csplit + cb) = *(uint4*)lv;
        }
    } else if (EPI == 1) {
        float* C = (float*)Cgv + (size_t)zb * sCb + (size_t)zh * sCh + (size_t)gr * ldc + gc;
        const int* mrow = maskg + (size_t)zb * sMb + (size_t)gr * NL + gc;
#pragma unroll
        for (int j4 = 0; j4 < 16; j4++) {
            int4 m = *(const int4*)(mrow + j4 * 4);
            int mm[4] = {m.x, m.y, m.z, m.w};
            float ov[4];
#pragma unroll
            for (int j = 0; j < 4; j++) {
                float s = crow[j4 * 4 + j] * 0.0625f;   // 1/sqrt(256)
                s = fminf(15.f, fmaxf(-15.f, s));
                ov[j] = mm[j] ? s : 30000.f;
            }
            *(float4*)(C + j4 * 4) = *(float4*)ov;
        }
    } else {  // EPI == 3: plain fp32
        float* C = (float*)Cgv + (size_t)zb * sCb + (size_t)zh * sCh + (size_t)gr * ldc + gc;
#pragma unroll
        for (int j4 = 0; j4 < 16; j4++) {
            float ov[4] = {crow[j4 * 4], crow[j4 * 4 + 1], crow[j4 * 4 + 2], crow[j4 * 4 + 3]};
            *(float4*)(C + j4 * 4) = *(float4*)ov;
        }
    }
}

// ---------------------------------------------------------------------------
// masked softmax, in place (sentinel > 1000 = masked)
// ---------------------------------------------------------------------------
__global__ void __launch_bounds__(256) softmax_k(float* __restrict__ attn)
{
    __shared__ float sh[8];
    float* p = attn + (size_t)blockIdx.x * 1024;
    const int t = threadIdx.x;

    float4 v4 = ((const float4*)p)[t];
    float x[4] = {v4.x, v4.y, v4.z, v4.w};
    bool msk[4];
    float mx = -1e30f;
#pragma unroll
    for (int i = 0; i < 4; i++) {
        msk[i] = (x[i] > 1000.f);
        if (msk[i]) x[i] = 0.f;
        mx = fmaxf(mx, x[i]);
    }
#pragma unroll
    for (int o = 16; o; o >>= 1) mx = fmaxf(mx, __shfl_xor_sync(0xffffffffu, mx, o));
    if ((t & 31) == 0) sh[t >> 5] = mx;
    __syncthreads();
    mx = sh[0];
#pragma unroll
    for (int i = 1; i < 8; i++) mx = fmaxf(mx, sh[i]);

    float e[4], s = 0.f;
#pragma unroll
    for (int i = 0; i < 4; i++) {
        e[i] = msk[i] ? 0.f : __expf(x[i] - mx);
        s += e[i];
    }
#pragma unroll
    for (int o = 16; o; o >>= 1) s += __shfl_xor_sync(0xffffffffu, s, o);
    __syncthreads();
    if ((t & 31) == 0) sh[t >> 5] = s;
    __syncthreads();
    s = 0.f;
#pragma unroll
    for (int i = 0; i < 8; i++) s += sh[i];

    const float inv = 1.f / (s + 1e-6f);
    float4 o4 = {e[0] * inv, e[1] * inv, e[2] * inv, e[3] * inv};
    ((float4*)p)[t] = o4;
}

// ---------------------------------------------------------------------------
// split-K reduce + bias + residual + LayerNorm
// ---------------------------------------------------------------------------
__global__ void __launch_bounds__(256) fc_ln_k(
    const float* __restrict__ tmp, const float* __restrict__ fcb,
    const float* __restrict__ resid, const float* __restrict__ lg,
    const float* __restrict__ lb, float* __restrict__ out)
{
    __shared__ float shs[8], shq[8];
    const size_t o = (size_t)blockIdx.x * 256 + threadIdx.x;
    const int t = threadIdx.x;

    float v = tmp[o] + tmp[o + 1048576] + tmp[o + 2097152] + tmp[o + 3145728]
            + fcb[t] + resid[o];

    float s = v, qq = v * v;
#pragma unroll
    for (int d = 16; d; d >>= 1) {
        s  += __shfl_xor_sync(0xffffffffu, s, d);
        qq += __shfl_xor_sync(0xffffffffu, qq, d);
    }
    if ((t & 31) == 0) { shs[t >> 5] = s; shq[t >> 5] = qq; }
    __syncthreads();
    s = 0.f; qq = 0.f;
#pragma unroll
    for (int i = 0; i < 8; i++) { s += shs[i]; qq += shq[i]; }

    const float mean = s * (1.f / 256.f);
    const float var  = qq * (1.f / 256.f) - mean * mean;
    out[o] = (v - mean) * rsqrtf(var + 1e-5f) * lg[t] + lb[t];
}

// ---------------------------------------------------------------------------
extern "C" void kernel_launch(void* const* d_in, const int* in_sizes, int n_in,
                              void* d_out, int out_size)
{
    const float* q    = (const float*)d_in[0];
    const int*   mask = (const int*)  d_in[1];
    const float* k    = (const float*)d_in[2];
    const float* v    = (const float*)d_in[3];
    const float* w_qs = (const float*)d_in[4];
    const float* w_ks = (const float*)d_in[5];
    const float* w_vs = (const float*)d_in[6];
    const float* fc_w = (const float*)d_in[7];
    const float* fc_b = (const float*)d_in[8];
    const float* ln_g = (const float*)d_in[9];
    const float* ln_b = (const float*)d_in[10];

    float* out  = (float*)d_out;
    float* attn = out + (size_t)NBL * ND;

    __nv_bfloat16 *qp, *kp, *vp, *wqp, *wkp, *wvp, *fcwp, *qhp, *khp, *vht, *hop;
    float* tmp;
    cudaGetSymbolAddress((void**)&qp,   g_qp);
    cudaGetSymbolAddress((void**)&kp,   g_kp);
    cudaGetSymbolAddress((void**)&vp,   g_vp);
    cudaGetSymbolAddress((void**)&wqp,  g_wqp);
    cudaGetSymbolAddress((void**)&wkp,  g_wkp);
    cudaGetSymbolAddress((void**)&wvp,  g_wvp);
    cudaGetSymbolAddress((void**)&fcwp, g_fcwp);
    cudaGetSymbolAddress((void**)&qhp,  g_qhp);
    cudaGetSymbolAddress((void**)&khp,  g_khp);
    cudaGetSymbolAddress((void**)&vht,  g_vht);
    cudaGetSymbolAddress((void**)&hop,  g_hop);
    cudaGetSymbolAddress((void**)&tmp,  g_tmp);

    cudaFuncSetAttribute(tgemm<0, 0>, cudaFuncAttributeMaxDynamicSharedMemorySize, SMEMB);
    cudaFuncSetAttribute(tgemm<0, 1>, cudaFuncAttributeMaxDynamicSharedMemorySize, SMEMB);
    cudaFuncSetAttribute(tgemm<1, 0>, cudaFuncAttributeMaxDynamicSharedMemorySize, SMEMB);
    cudaFuncSetAttribute(tgemm<0, 3>, cudaFuncAttributeMaxDynamicSharedMemorySize, SMEMB);

    // ---- convert fp32 -> bf16 hi/lo planes ----
    cvt_k<<<(NBL * ND / 4 + 255) / 256, 256>>>(q, qp, qp + NBL * ND, NBL * ND / 4);
    cvt_k<<<(NBL * ND / 4 + 255) / 256, 256>>>(k, kp, kp + NBL * ND, NBL * ND / 4);
    cvt_k<<<(NBL * ND / 4 + 255) / 256, 256>>>(v, vp, vp + NBL * ND, NBL * ND / 4);
    cvt_k<<<(NHD * ND / 4 + 255) / 256, 256>>>(w_qs, wqp, wqp + NHD * ND, NHD * ND / 4);
    cvt_k<<<(NHD * ND / 4 + 255) / 256, 256>>>(w_ks, wkp, wkp + NHD * ND, NHD * ND / 4);
    cvt_k<<<(NHD * ND / 4 + 255) / 256, 256>>>(w_vs, wvp, wvp + NHD * ND, NHD * ND / 4);
    cvt_k<<<(ND * NHD / 4 + 255) / 256, 256>>>(fc_w, fcwp, fcwp + ND * NHD, ND * NHD / 4);

    const long QKSZ = (long)NBL * ND;        // 1048576
    const long WSZ  = (long)NHD * ND;        // 524288
    const long BIG  = (long)NBL * NHD;       // 8388608

    // ---- Q, K projections: [4096,2048] = x @ w^T ----
    tgemm<0, 0><<<dim3(16, 32, 1), 256, SMEMB>>>(
        qp, QKSZ, ND, wqp, WSZ, ND, qhp, NHD, BIG, ND, 1,
        0, 0, 0, 0, 0, 0, nullptr, 0);
    tgemm<0, 0><<<dim3(16, 32, 1), 256, SMEMB>>>(
        kp, QKSZ, ND, wkp, WSZ, ND, khp, NHD, BIG, ND, 1,
        0, 0, 0, 0, 0, 0, nullptr, 0);

    // ---- V projection, transposed output: vht[hd, token] = w_vs @ v^T ----
    tgemm<0, 0><<<dim3(32, 16, 1), 256, SMEMB>>>(
        wvp, WSZ, ND, vp, QKSZ, ND, vht, NBL, BIG, ND, 1,
        0, 0, 0, 0, 0, 0, nullptr, 0);

    // ---- scores: per (b,h)  attn[(h*B+b)] = qh @ kh^T /16, clip, mask ----
    tgemm<0, 1><<<dim3(8, 8, 32), 256, SMEMB>>>(
        qhp, BIG, NHD, khp, BIG, NHD, attn, NL, 0, ND, NB,
        (long)NL * NHD, (long)ND,
        (long)NL * NHD, (long)ND,
        (long)NL * NL, (long)NB * NL * NL,
        mask, (long)NL * NL);

    // ---- masked softmax in place ----
    softmax_k<<<NH * NB * NL, 256>>>(attn);

    // ---- attn @ V: hop[b,l, h*256+d] (A = attn fp32, split on the fly) ----
    tgemm<1, 0><<<dim3(2, 8, 32), 256, SMEMB>>>(
        attn, 0, NL, vht, BIG, NBL, hop, NHD, BIG, NL, NB,
        (long)NL * NL, (long)NB * NL * NL,
        (long)NL, (long)ND * NBL,
        (long)NL * NHD, (long)ND,
        nullptr, 0);

    // ---- fc: split-K = 4 -> fp32 partials ----
    tgemm<0, 3><<<dim3(2, 32, 4), 256, SMEMB>>>(
        hop, BIG, NHD, fcwp, (long)ND * NHD, NHD, tmp, ND, 0, 512, 1,
        0, 512, 0, 512, 0, (long)NBL * ND, nullptr, 0);

    // ---- reduce + bias + residual + LayerNorm ----
    fc_ln_k<<<NBL, 256>>>(tmp, fc_b, q, ln_g, ln_b, out);
}

// round 4
// speedup vs baseline: 1.7113x; 1.2810x over previous
#include <cuda_runtime.h>
#include <cuda_bf16.h>
#include <mma.h>
#include <cstdint>

using namespace nvcuda;

#define NB 4
#define NL 1024
#define ND 256
#define NH 8
#define NHD 2048
#define NBL 4096
#define ATT ((size_t)NB * NH * NL * NL)   // 33,554,432 attn elems

#define LDS_AB 72              // BK(64) + 8 pad -> 144B rows, LDSM conflict-free
#define PLE (128 * LDS_AB)     // elems per plane tile (9216)
#define PLB (PLE * 2)          // bytes per plane tile (18432)
#define STGB (4 * PLB)         // bytes per stage: Ahi|Alo|Bhi|Blo (73728)
#define LDC_S 132              // epilogue smem stride (floats)
#define SMEMB (2 * STGB)       // 147456 B (>= Cs 67584 B)

// ---------------------------------------------------------------------------
// cp.async helpers (Ampere+, plain sm_103 OK)
// ---------------------------------------------------------------------------
__device__ __forceinline__ uint32_t smem_u32(const void* p) {
    uint32_t a;
    asm("{ .reg .u64 t; cvta.to.shared.u64 t, %1; cvt.u32.u64 %0, t; }" : "=r"(a) : "l"(p));
    return a;
}
#define CP_ASYNC16(dst, src) \
    asm volatile("cp.async.cg.shared.global [%0], [%1], 16;" :: "r"(dst), "l"(src) : "memory")
#define CP_COMMIT() asm volatile("cp.async.commit_group;" ::: "memory")
#define CP_WAIT0()  asm volatile("cp.async.wait_group 0;" ::: "memory")
#define CP_WAIT1()  asm volatile("cp.async.wait_group 1;" ::: "memory")

// ---------------------------------------------------------------------------
// scratch (device globals — allocations forbidden)
// ---------------------------------------------------------------------------
static __device__ __align__(16) __nv_bfloat16 g_qp[2 * NBL * ND];
static __device__ __align__(16) __nv_bfloat16 g_kp[2 * NBL * ND];
static __device__ __align__(16) __nv_bfloat16 g_vp[2 * NBL * ND];
static __device__ __align__(16) __nv_bfloat16 g_wqp[2 * NHD * ND];
static __device__ __align__(16) __nv_bfloat16 g_wkp[2 * NHD * ND];
static __device__ __align__(16) __nv_bfloat16 g_wvp[2 * NHD * ND];
static __device__ __align__(16) __nv_bfloat16 g_fcwp[2 * ND * NHD];
static __device__ __align__(16) __nv_bfloat16 g_qhp[2 * (size_t)NBL * NHD];
static __device__ __align__(16) __nv_bfloat16 g_khp[2 * (size_t)NBL * NHD];
static __device__ __align__(16) __nv_bfloat16 g_vht[2 * (size_t)NHD * NBL];
static __device__ __align__(16) __nv_bfloat16 g_hop[2 * (size_t)NBL * NHD];
static __device__ __align__(16) __nv_bfloat16 g_ap[2 * ATT];   // softmaxed attn planes
static __device__ float g_tmp[(size_t)4 * NBL * ND];

// ---------------------------------------------------------------------------
// fp32 -> (hi, lo) bf16 planes
// ---------------------------------------------------------------------------
__global__ void __launch_bounds__(256) cvt_k(const float* __restrict__ x,
                                             __nv_bfloat16* __restrict__ hi,
                                             __nv_bfloat16* __restrict__ lo, int n4) {
    int i = blockIdx.x * 256 + threadIdx.x;
    if (i >= n4) return;
    float4 v = *((const float4*)x + i);
    float f[4] = {v.x, v.y, v.z, v.w};
    __align__(8) __nv_bfloat16 h[4], l[4];
#pragma unroll
    for (int j = 0; j < 4; j++) {
        h[j] = __float2bfloat16(f[j]);
        l[j] = __float2bfloat16(f[j] - __bfloat162float(h[j]));
    }
    *(uint2*)(hi + (size_t)i * 4) = *(uint2*)h;
    *(uint2*)(lo + (size_t)i * 4) = *(uint2*)l;
}

// ---------------------------------------------------------------------------
// WMMA bf16x3 GEMM, cp.async 2-stage pipeline, BK=64.
//   C[128x128 tile] = A @ B^T, fp32 accumulate; A/B are bf16 hi/lo planes.
//   EPI 0: write bf16 hi/lo pairs   1: scores (scale/clip/mask -> sentinel)
//   EPI 3: plain fp32 (fc split-K partials)
// 256 threads (8 warps, 2x4), warp tile 64x32.
// ---------------------------------------------------------------------------
template <int EPI>
__global__ void __launch_bounds__(256, 1) tgemm(
    const __nv_bfloat16* __restrict__ Ag, long Asplit, int lda,
    const __nv_bfloat16* __restrict__ Bg, long Bsplit, int ldb,
    void* __restrict__ Cgv, int ldc, long Csplit,
    int K, int nBdim,
    long sAb, long sAh, long sBb, long sBh, long sCb, long sCh,
    const int* __restrict__ maskg, long sMb)
{
    extern __shared__ __align__(16) char sm[];
    const uint32_t smb = smem_u32(sm);
    float* Cs = (float*)sm;   // epilogue staging (reuses pipeline smem)

    const int tid = threadIdx.x;
    const int wid = tid >> 5;
    const int wm = wid & 1;   // warp row (2 x 64)
    const int wn = wid >> 1;  // warp col (4 x 32)

    const int z = blockIdx.z, zb = z % nBdim, zh = z / nBdim;
    const __nv_bfloat16* Ap = Ag + (size_t)zb * sAb + (size_t)zh * sAh;
    const __nv_bfloat16* Bp = Bg + (size_t)zb * sBb + (size_t)zh * sBh;

    const int rowBase = blockIdx.y * 128;
    const int colBase = blockIdx.x * 128;

    wmma::fragment<wmma::accumulator, 16, 16, 16, float> acc[4][2];
#pragma unroll
    for (int i = 0; i < 4; i++)
#pragma unroll
        for (int j = 0; j < 2; j++) wmma::fill_fragment(acc[i][j], 0.f);

    // issue one stage of async loads: 4 planes x 1024 16B-chunks
    auto ldst = [&](int t, int s) {
        const int ko = t * 64;
        const uint32_t sb = smb + s * STGB;
#pragma unroll
        for (int i = 0; i < 4; i++) {
            const int c = tid + i * 256;          // 0..1023
            const int row = c >> 3, col = (c & 7) * 8;
            const uint32_t soff = (uint32_t)(row * LDS_AB + col) * 2;
            const __nv_bfloat16* pa = Ap + (size_t)(rowBase + row) * lda + ko + col;
            CP_ASYNC16(sb + soff,           pa);
            CP_ASYNC16(sb + PLB + soff,     pa + Asplit);
            const __nv_bfloat16* pb = Bp + (size_t)(colBase + row) * ldb + ko + col;
            CP_ASYNC16(sb + 2 * PLB + soff, pb);
            CP_ASYNC16(sb + 3 * PLB + soff, pb + Bsplit);
        }
        CP_COMMIT();
    };

    auto compute = [&](int s) {
        const __nv_bfloat16* base = (const __nv_bfloat16*)(sm + s * STGB);
        const __nv_bfloat16* Ah0 = base + wm * 64 * LDS_AB;
        const __nv_bfloat16* Al0 = Ah0 + PLE;
        const __nv_bfloat16* Bh0 = base + 2 * PLE + wn * 32 * LDS_AB;
        const __nv_bfloat16* Bl0 = Bh0 + PLE;
#pragma unroll
        for (int ks = 0; ks < 4; ks++) {
            wmma::fragment<wmma::matrix_a, 16, 16, 16, __nv_bfloat16, wmma::row_major> fah[4], fal[4];
            wmma::fragment<wmma::matrix_b, 16, 16, 16, __nv_bfloat16, wmma::col_major> fbh[2], fbl[2];
#pragma unroll
            for (int i = 0; i < 4; i++) {
                wmma::load_matrix_sync(fah[i], Ah0 + i * 16 * LDS_AB + ks * 16, LDS_AB);
                wmma::load_matrix_sync(fal[i], Al0 + i * 16 * LDS_AB + ks * 16, LDS_AB);
            }
#pragma unroll
            for (int j = 0; j < 2; j++) {
                wmma::load_matrix_sync(fbh[j], Bh0 + j * 16 * LDS_AB + ks * 16, LDS_AB);
                wmma::load_matrix_sync(fbl[j], Bl0 + j * 16 * LDS_AB + ks * 16, LDS_AB);
            }
#pragma unroll
            for (int i = 0; i < 4; i++)
#pragma unroll
                for (int j = 0; j < 2; j++) {
                    wmma::mma_sync(acc[i][j], fah[i], fbh[j], acc[i][j]);
                    wmma::mma_sync(acc[i][j], fah[i], fbl[j], acc[i][j]);
                    wmma::mma_sync(acc[i][j], fal[i], fbh[j], acc[i][j]);
                }
        }
    };

    // ---- pipelined mainloop (T >= 4 always here) ----
    const int T = K >> 6;
    ldst(0, 0);
    ldst(1, 1);
    for (int t = 0; t < T; t++) {
        if (t == T - 1) { CP_WAIT0(); } else { CP_WAIT1(); }
        __syncthreads();
        compute(t & 1);
        __syncthreads();
        if (t + 2 < T) ldst(t + 2, t & 1);
    }

    // ---- epilogue: stage accumulators through SMEM ----
#pragma unroll
    for (int i = 0; i < 4; i++)
#pragma unroll
        for (int j = 0; j < 2; j++)
            wmma::store_matrix_sync(Cs + (size_t)(wm * 64 + i * 16) * LDC_S + wn * 32 + j * 16,
                                    acc[i][j], LDC_S, wmma::mem_row_major);
    __syncthreads();

    const int row = tid >> 1;
    const int ch  = (tid & 1) * 64;
    const float* crow = Cs + (size_t)row * LDC_S + ch;
    const int gr = rowBase + row;
    const int gc = colBase + ch;

    if (EPI == 0) {
        __nv_bfloat16* Ch = (__nv_bfloat16*)Cgv + (size_t)zb * sCb + (size_t)zh * sCh +
                            (size_t)gr * ldc + gc;
#pragma unroll
        for (int cb = 0; cb < 64; cb += 8) {
            __align__(16) __nv_bfloat16 hv[8], lv[8];
#pragma unroll
            for (int j = 0; j < 8; j++) {
                float v = crow[cb + j];
                hv[j] = __float2bfloat16(v);
                lv[j] = __float2bfloat16(v - __bfloat162float(hv[j]));
            }
            *(uint4*)(Ch + cb)          = *(uint4*)hv;
            *(uint4*)(Ch + Csplit + cb) = *(uint4*)lv;
        }
    } else if (EPI == 1) {
        float* C = (float*)Cgv + (size_t)zb * sCb + (size_t)zh * sCh + (size_t)gr * ldc + gc;
        const int* mrow = maskg + (size_t)zb * sMb + (size_t)gr * NL + gc;
#pragma unroll
        for (int j4 = 0; j4 < 16; j4++) {
            int4 m = *(const int4*)(mrow + j4 * 4);
            int mm[4] = {m.x, m.y, m.z, m.w};
            float ov[4];
#pragma unroll
            for (int j = 0; j < 4; j++) {
                float s = crow[j4 * 4 + j] * 0.0625f;   // 1/sqrt(256)
                s = fminf(15.f, fmaxf(-15.f, s));
                ov[j] = mm[j] ? s : 30000.f;
            }
            *(float4*)(C + j4 * 4) = *(float4*)ov;
        }
    } else {  // EPI == 3: plain fp32
        float* C = (float*)Cgv + (size_t)zb * sCb + (size_t)zh * sCh + (size_t)gr * ldc + gc;
#pragma unroll
        for (int j4 = 0; j4 < 16; j4++) {
            float ov[4] = {crow[j4 * 4], crow[j4 * 4 + 1], crow[j4 * 4 + 2], crow[j4 * 4 + 3]};
            *(float4*)(C + j4 * 4) = *(float4*)ov;
        }
    }
}

// ---------------------------------------------------------------------------
// masked softmax in place (sentinel > 1000 = masked); also emits bf16 hi/lo
// planes of the result for the attn@V GEMM.
// ---------------------------------------------------------------------------
__global__ void __launch_bounds__(256) softmax_k(float* __restrict__ attn,
                                                 __nv_bfloat16* __restrict__ ap)
{
    __shared__ float sh[8];
    const size_t rbase = (size_t)blockIdx.x * 1024;
    float* p = attn + rbase;
    const int t = threadIdx.x;

    float4 v4 = ((const float4*)p)[t];
    float x[4] = {v4.x, v4.y, v4.z, v4.w};
    bool msk[4];
    float mx = -1e30f;
#pragma unroll
    for (int i = 0; i < 4; i++) {
        msk[i] = (x[i] > 1000.f);
        if (msk[i]) x[i] = 0.f;
        mx = fmaxf(mx, x[i]);
    }
#pragma unroll
    for (int o = 16; o; o >>= 1) mx = fmaxf(mx, __shfl_xor_sync(0xffffffffu, mx, o));
    if ((t & 31) == 0) sh[t >> 5] = mx;
    __syncthreads();
    mx = sh[0];
#pragma unroll
    for (int i = 1; i < 8; i++) mx = fmaxf(mx, sh[i]);

    float e[4], s = 0.f;
#pragma unroll
    for (int i = 0; i < 4; i++) {
        e[i] = msk[i] ? 0.f : __expf(x[i] - mx);
        s += e[i];
    }
#pragma unroll
    for (int o = 16; o; o >>= 1) s += __shfl_xor_sync(0xffffffffu, s, o);
    __syncthreads();
    if ((t & 31) == 0) sh[t >> 5] = s;
    __syncthreads();
    s = 0.f;
#pragma unroll
    for (int i = 0; i < 8; i++) s += sh[i];

    const float inv = 1.f / (s + 1e-6f);
    float ov[4] = {e[0] * inv, e[1] * inv, e[2] * inv, e[3] * inv};
    ((float4*)p)[t] = *(float4*)ov;

    __align__(8) __nv_bfloat16 h[4], l[4];
#pragma unroll
    for (int i = 0; i < 4; i++) {
        h[i] = __float2bfloat16(ov[i]);
        l[i] = __float2bfloat16(ov[i] - __bfloat162float(h[i]));
    }
    const size_t idx = rbase + (size_t)t * 4;
    *(uint2*)(ap + idx)       = *(uint2*)h;
    *(uint2*)(ap + ATT + idx) = *(uint2*)l;
}

// ---------------------------------------------------------------------------
// split-K reduce + bias + residual + LayerNorm
// ---------------------------------------------------------------------------
__global__ void __launch_bounds__(256) fc_ln_k(
    const float* __restrict__ tmp, const float* __restrict__ fcb,
    const float* __restrict__ resid, const float* __restrict__ lg,
    const float* __restrict__ lb, float* __restrict__ out)
{
    __shared__ float shs[8], shq[8];
    const size_t o = (size_t)blockIdx.x * 256 + threadIdx.x;
    const int t = threadIdx.x;

    float v = tmp[o] + tmp[o + 1048576] + tmp[o + 2097152] + tmp[o + 3145728]
            + fcb[t] + resid[o];

    float s = v, qq = v * v;
#pragma unroll
    for (int d = 16; d; d >>= 1) {
        s  += __shfl_xor_sync(0xffffffffu, s, d);
        qq += __shfl_xor_sync(0xffffffffu, qq, d);
    }
    if ((t & 31) == 0) { shs[t >> 5] = s; shq[t >> 5] = qq; }
    __syncthreads();
    s = 0.f; qq = 0.f;
#pragma unroll
    for (int i = 0; i < 8; i++) { s += shs[i]; qq += shq[i]; }

    const float mean = s * (1.f / 256.f);
    const float var  = qq * (1.f / 256.f) - mean * mean;
    out[o] = (v - mean) * rsqrtf(var + 1e-5f) * lg[t] + lb[t];
}

// ---------------------------------------------------------------------------
extern "C" void kernel_launch(void* const* d_in, const int* in_sizes, int n_in,
                              void* d_out, int out_size)
{
    const float* q    = (const float*)d_in[0];
    const int*   mask = (const int*)  d_in[1];
    const float* k    = (const float*)d_in[2];
    const float* v    = (const float*)d_in[3];
    const float* w_qs = (const float*)d_in[4];
    const float* w_ks = (const float*)d_in[5];
    const float* w_vs = (const float*)d_in[6];
    const float* fc_w = (const float*)d_in[7];
    const float* fc_b = (const float*)d_in[8];
    const float* ln_g = (const float*)d_in[9];
    const float* ln_b = (const float*)d_in[10];

    float* out  = (float*)d_out;
    float* attn = out + (size_t)NBL * ND;

    __nv_bfloat16 *qp, *kp, *vp, *wqp, *wkp, *wvp, *fcwp, *qhp, *khp, *vht, *hop, *ap;
    float* tmp;
    cudaGetSymbolAddress((void**)&qp,   g_qp);
    cudaGetSymbolAddress((void**)&kp,   g_kp);
    cudaGetSymbolAddress((void**)&vp,   g_vp);
    cudaGetSymbolAddress((void**)&wqp,  g_wqp);
    cudaGetSymbolAddress((void**)&wkp,  g_wkp);
    cudaGetSymbolAddress((void**)&wvp,  g_wvp);
    cudaGetSymbolAddress((void**)&fcwp, g_fcwp);
    cudaGetSymbolAddress((void**)&qhp,  g_qhp);
    cudaGetSymbolAddress((void**)&khp,  g_khp);
    cudaGetSymbolAddress((void**)&vht,  g_vht);
    cudaGetSymbolAddress((void**)&hop,  g_hop);
    cudaGetSymbolAddress((void**)&ap,   g_ap);
    cudaGetSymbolAddress((void**)&tmp,  g_tmp);

    cudaFuncSetAttribute(tgemm<0>, cudaFuncAttributeMaxDynamicSharedMemorySize, SMEMB);
    cudaFuncSetAttribute(tgemm<1>, cudaFuncAttributeMaxDynamicSharedMemorySize, SMEMB);
    cudaFuncSetAttribute(tgemm<3>, cudaFuncAttributeMaxDynamicSharedMemorySize, SMEMB);

    // ---- convert fp32 -> bf16 hi/lo planes ----
    cvt_k<<<(NBL * ND / 4 + 255) / 256, 256>>>(q, qp, qp + NBL * ND, NBL * ND / 4);
    cvt_k<<<(NBL * ND / 4 + 255) / 256, 256>>>(k, kp, kp + NBL * ND, NBL * ND / 4);
    cvt_k<<<(NBL * ND / 4 + 255) / 256, 256>>>(v, vp, vp + NBL * ND, NBL * ND / 4);
    cvt_k<<<(NHD * ND / 4 + 255) / 256, 256>>>(w_qs, wqp, wqp + NHD * ND, NHD * ND / 4);
    cvt_k<<<(NHD * ND / 4 + 255) / 256, 256>>>(w_ks, wkp, wkp + NHD * ND, NHD * ND / 4);
    cvt_k<<<(NHD * ND / 4 + 255) / 256, 256>>>(w_vs, wvp, wvp + NHD * ND, NHD * ND / 4);
    cvt_k<<<(ND * NHD / 4 + 255) / 256, 256>>>(fc_w, fcwp, fcwp + ND * NHD, ND * NHD / 4);

    const long QKSZ = (long)NBL * ND;        // 1048576
    const long WSZ  = (long)NHD * ND;        // 524288
    const long BIG  = (long)NBL * NHD;       // 8388608

    // ---- Q, K projections: [4096,2048] = x @ w^T ----
    tgemm<0><<<dim3(16, 32, 1), 256, SMEMB>>>(
        qp, QKSZ, ND, wqp, WSZ, ND, qhp, NHD, BIG, ND, 1,
        0, 0, 0, 0, 0, 0, nullptr, 0);
    tgemm<0><<<dim3(16, 32, 1), 256, SMEMB>>>(
        kp, QKSZ, ND, wkp, WSZ, ND, khp, NHD, BIG, ND, 1,
        0, 0, 0, 0, 0, 0, nullptr, 0);

    // ---- V projection, transposed output: vht[hd, token] = w_vs @ v^T ----
    tgemm<0><<<dim3(32, 16, 1), 256, SMEMB>>>(
        wvp, WSZ, ND, vp, QKSZ, ND, vht, NBL, BIG, ND, 1,
        0, 0, 0, 0, 0, 0, nullptr, 0);

    // ---- scores: per (b,h)  attn[(h*B+b)] = qh @ kh^T /16, clip, mask ----
    tgemm<1><<<dim3(8, 8, 32), 256, SMEMB>>>(
        qhp, BIG, NHD, khp, BIG, NHD, attn, NL, 0, ND, NB,
        (long)NL * NHD, (long)ND,
        (long)NL * NHD, (long)ND,
        (long)NL * NL, (long)NB * NL * NL,
        mask, (long)NL * NL);

    // ---- masked softmax in place + bf16 plane emission ----
    softmax_k<<<NH * NB * NL, 256>>>(attn, ap);

    // ---- attn @ V: hop[b,l, h*256+d] ----
    tgemm<0><<<dim3(2, 8, 32), 256, SMEMB>>>(
        ap, (long)ATT, NL, vht, BIG, NBL, hop, NHD, BIG, NL, NB,
        (long)NL * NL, (long)NB * NL * NL,
        (long)NL, (long)ND * NBL,
        (long)NL * NHD, (long)ND,
        nullptr, 0);

    // ---- fc: split-K = 4 -> fp32 partials ----
    tgemm<3><<<dim3(2, 32, 4), 256, SMEMB>>>(
        hop, BIG, NHD, fcwp, (long)ND * NHD, NHD, tmp, ND, 0, 512, 1,
        0, 512, 0, 512, 0, (long)NBL * ND, nullptr, 0);

    // ---- reduce + bias + residual + LayerNorm ----
    fc_ln_k<<<NBL, 256>>>(tmp, fc_b, q, ln_g, ln_b, out);
}